// round 12
// baseline (speedup 1.0000x reference)
#include <cuda_runtime.h>
#include <cstdint>

// Problem constants
#define B_  64
#define T_  2048
#define H_  512
#define S_  512
#define K_  128
#define V_  128

#define ROWS_PER_WARP 16
#define CHUNKS_PER_B  (T_ / ROWS_PER_WARP)          // 128
#define NWARPS_TOT    (B_ * CHUNKS_PER_B)           // 8192

// Scratch (device globals — no allocation allowed)
__device__ float g_q [B_ * K_];                 // query = ds@Ws^T + bs
__device__ float g_qh[B_ * H_];                 // Wh^T @ query per batch
__device__ float g_qc[B_];                      // query . bh
__device__ float g_energy[B_ * T_];             // raw energies
__device__ float g_pM [NWARPS_TOT];             // per-warp partial max
__device__ float g_pSA[NWARPS_TOT];             // per-warp partial sum(all exp)
__device__ float g_pSV[NWARPS_TOT];             // per-warp partial sum(valid exp)
__device__ float g_part[NWARPS_TOT * H_];       // per-warp partial weighted L sums
__device__ float g_ctxh[B_ * H_];               // merged, inv-scaled context in H
__device__ float g_M[B_], g_inv[B_], g_A[B_];   // per-batch softmax stats

__device__ __forceinline__ float warp_sum(float v) {
#pragma unroll
    for (int o = 16; o; o >>= 1) v += __shfl_xor_sync(0xffffffffu, v, o);
    return v;
}
__device__ __forceinline__ void warp_sum2(float& a, float& b) {
#pragma unroll
    for (int o = 16; o; o >>= 1) {
        a += __shfl_xor_sync(0xffffffffu, a, o);
        b += __shfl_xor_sync(0xffffffffu, b, o);
    }
}
__device__ __forceinline__ float warp_max(float v) {
#pragma unroll
    for (int o = 16; o; o >>= 1) v = fmaxf(v, __shfl_xor_sync(0xffffffffu, v, o));
    return v;
}

// ---------------------------------------------------------------------------
// Kernel 1a: query[b,k] = ds[b] . Ws[k] + bs[k].  Warp per (b,k).
// ---------------------------------------------------------------------------
__global__ void __launch_bounds__(256) k_query(const float* __restrict__ ds,
                                               const float* __restrict__ Ws,
                                               const float* __restrict__ bs) {
    const int w    = blockIdx.x * 8 + (threadIdx.x >> 5);
    const int lane = threadIdx.x & 31;
    const int b = w >> 7;
    const int k = w & (K_ - 1);

    const float4* d4 = (const float4*)(ds + b * S_);
    const float4* w4 = (const float4*)(Ws + k * S_);
    float acc = 0.f;
#pragma unroll
    for (int j = 0; j < 4; j++) {
        float4 dv = d4[lane + 32 * j];
        float4 wv = w4[lane + 32 * j];
        acc += dv.x * wv.x + dv.y * wv.y + dv.z * wv.z + dv.w * wv.w;
    }
    acc = warp_sum(acc);
    if (lane == 0) g_q[b * K_ + k] = acc + bs[k];
}

// ---------------------------------------------------------------------------
// Kernel 1b: qh[b,h] = sum_k q[b,k]*Wh[k,h] (thread per (b,h)); qc folded in.
// ---------------------------------------------------------------------------
__global__ void __launch_bounds__(256) k_qh(const float* __restrict__ Wh,
                                            const float* __restrict__ bh) {
    const int tid = threadIdx.x;
    const int idx = blockIdx.x * 256 + tid;
    const int b = idx >> 9;
    const int h = idx & (H_ - 1);

    const float* q = g_q + b * K_;
    const float* whc = Wh + h;
    float acc = 0.f;
#pragma unroll 8
    for (int k = 0; k < K_; k++)
        acc += q[k] * whc[k * H_];
    g_qh[b * H_ + h] = acc;

    if ((blockIdx.x & 1) == 0 && tid < 32) {
        float4 qv  = ((const float4*)q)[tid];
        float4 bhv = ((const float4*)bh)[tid];
        float p = qv.x * bhv.x + qv.y * bhv.y + qv.z * bhv.z + qv.w * bhv.w;
        p = warp_sum(p);
        if (tid == 0) g_qc[b] = p;
    }
}

// ---------------------------------------------------------------------------
// Kernel 2: warp-level flash pass, 16 t-rows per warp, pairs, BRANCHLESS
// online rescale (f = exp(M - mN); first iter f = exp(-inf) = 0, no-change
// iters f = 1 exactly) and MANUAL software pipeline (pair t+2 loads issued
// before pair t is processed -> loads always in flight across shfl/exp).
// 8192 warps = 1024 blocks x 256 threads.  Streams L exactly once.
// ---------------------------------------------------------------------------
__global__ void __launch_bounds__(256) k_flash(const float* __restrict__ L,
                                               const int* __restrict__ lens) {
    const int w    = blockIdx.x * 8 + (threadIdx.x >> 5);
    const int lane = threadIdx.x & 31;
    const int b    = w >> 7;                       // / CHUNKS_PER_B
    const int t0   = (w & (CHUNKS_PER_B - 1)) * ROWS_PER_WARP;
    const int len  = lens[b];
    const int nv   = (b == 0) ? ROWS_PER_WARP
                              : min(max(len - t0, 0), ROWS_PER_WARP);

    const float4* qh4 = (const float4*)(g_qh + b * H_);
    const float4 q0 = qh4[lane +  0];
    const float4 q1 = qh4[lane + 32];
    const float4 q2 = qh4[lane + 64];
    const float4 q3 = qh4[lane + 96];
    const float  qc = g_qc[b];

    float M = __int_as_float(0xff800000), SA = 0.f, SV = 0.f;
    float4 a0 = make_float4(0.f, 0.f, 0.f, 0.f);
    float4 a1 = a0, a2 = a0, a3 = a0;

    const float4* Lr = (const float4*)(L + ((size_t)(b * T_ + t0)) * H_) + lane;

    // prologue: load pair 0
    float4 ca0 = Lr[0],   ca1 = Lr[32],  ca2 = Lr[64],  ca3 = Lr[96];
    float4 cb0 = Lr[128], cb1 = Lr[160], cb2 = Lr[192], cb3 = Lr[224];

#pragma unroll
    for (int t = 0; t < ROWS_PER_WARP; t += 2) {
        // prefetch pair t+2 (clamped: last iteration redundantly reloads t=14)
        const int tn = (t + 2 < ROWS_PER_WARP) ? t + 2 : ROWS_PER_WARP - 2;
        const float4* rn = Lr + (size_t)tn * 128;
        float4 na0 = rn[0],   na1 = rn[32],  na2 = rn[64],  na3 = rn[96];
        float4 nb0 = rn[128], nb1 = rn[160], nb2 = rn[192], nb3 = rn[224];

        float eA = ca0.x * q0.x + ca0.y * q0.y + ca0.z * q0.z + ca0.w * q0.w
                 + ca1.x * q1.x + ca1.y * q1.y + ca1.z * q1.z + ca1.w * q1.w
                 + ca2.x * q2.x + ca2.y * q2.y + ca2.z * q2.z + ca2.w * q2.w
                 + ca3.x * q3.x + ca3.y * q3.y + ca3.z * q3.z + ca3.w * q3.w;
        float eB = cb0.x * q0.x + cb0.y * q0.y + cb0.z * q0.z + cb0.w * q0.w
                 + cb1.x * q1.x + cb1.y * q1.y + cb1.z * q1.z + cb1.w * q1.w
                 + cb2.x * q2.x + cb2.y * q2.y + cb2.z * q2.z + cb2.w * q2.w
                 + cb3.x * q3.x + cb3.y * q3.y + cb3.z * q3.z + cb3.w * q3.w;
        warp_sum2(eA, eB);
        eA += qc; eB += qc;
        if (lane == 0) {
            g_energy[b * T_ + t0 + t]     = eA;
            g_energy[b * T_ + t0 + t + 1] = eB;
        }

        const float mN = fmaxf(M, fmaxf(eA, eB));
        const float f  = __expf(M - mN);         // 0 on first pair, 1 if no new max
        M = mN;
        const float xA = __expf(eA - M);
        const float xB = __expf(eB - M);
        const float xmA = (t     < nv) ? xA : 0.f;
        const float xmB = (t + 1 < nv) ? xB : 0.f;
        SA = SA * f + xA + xB;
        SV = SV * f + xmA + xmB;
        a0.x = a0.x * f + xmA * ca0.x + xmB * cb0.x;
        a0.y = a0.y * f + xmA * ca0.y + xmB * cb0.y;
        a0.z = a0.z * f + xmA * ca0.z + xmB * cb0.z;
        a0.w = a0.w * f + xmA * ca0.w + xmB * cb0.w;
        a1.x = a1.x * f + xmA * ca1.x + xmB * cb1.x;
        a1.y = a1.y * f + xmA * ca1.y + xmB * cb1.y;
        a1.z = a1.z * f + xmA * ca1.z + xmB * cb1.z;
        a1.w = a1.w * f + xmA * ca1.w + xmB * cb1.w;
        a2.x = a2.x * f + xmA * ca2.x + xmB * cb2.x;
        a2.y = a2.y * f + xmA * ca2.y + xmB * cb2.y;
        a2.z = a2.z * f + xmA * ca2.z + xmB * cb2.z;
        a2.w = a2.w * f + xmA * ca2.w + xmB * cb2.w;
        a3.x = a3.x * f + xmA * ca3.x + xmB * cb3.x;
        a3.y = a3.y * f + xmA * ca3.y + xmB * cb3.y;
        a3.z = a3.z * f + xmA * ca3.z + xmB * cb3.z;
        a3.w = a3.w * f + xmA * ca3.w + xmB * cb3.w;

        ca0 = na0; ca1 = na1; ca2 = na2; ca3 = na3;
        cb0 = nb0; cb1 = nb1; cb2 = nb2; cb3 = nb3;
    }

    if (lane == 0) { g_pM[w] = M; g_pSA[w] = SA; g_pSV[w] = SV; }
    float4* P = (float4*)(g_part + (size_t)w * H_) + lane;
    P[0]  = a0;
    P[32] = a1;
    P[64] = a2;
    P[96] = a3;
}

// ---------------------------------------------------------------------------
// Kernel 3: merge partials + per-batch stats (computed redundantly per block
// — removes the serial k_reduceMS launch).  Block covers 256 h of one batch:
// 128 blocks x 256 threads.  Writes g_ctxh, and (tid==0) g_M/g_inv/g_A.
// ---------------------------------------------------------------------------
__global__ void __launch_bounds__(256) k_merge(void) {
    const int blk = blockIdx.x;
    const int b   = blk >> 1;
    const int hb  = (blk & 1) << 8;
    const int tid = threadIdx.x;
    const int base = b * CHUNKS_PER_B;

    __shared__ float s_scale[CHUNKS_PER_B];
    __shared__ float s_red[8];
    __shared__ float s_M, s_inv;

    // --- max over 128 partials (threads 0..127) ---
    const float NEG_INF = __int_as_float(0xff800000);
    float m = (tid < CHUNKS_PER_B) ? g_pM[base + tid] : NEG_INF;
    float wm = warp_max(m);
    if ((tid & 31) == 0) s_red[tid >> 5] = wm;
    __syncthreads();
    if (tid == 0)
        s_M = fmaxf(fmaxf(s_red[0], s_red[1]), fmaxf(s_red[2], s_red[3]));
    __syncthreads();
    const float M = s_M;

    // --- scales + merged SA/SV ---
    float sa = 0.f, sv = 0.f;
    if (tid < CHUNKS_PER_B) {
        const float sc = __expf(m - M);
        s_scale[tid] = sc;
        sa = sc * g_pSA[base + tid];
        sv = sc * g_pSV[base + tid];
    }
    warp_sum2(sa, sv);
    __shared__ float sAr[8], sVr[8];
    if ((tid & 31) == 0) { sAr[tid >> 5] = sa; sVr[tid >> 5] = sv; }
    __syncthreads();
    if (tid == 0) {
        const float SA = sAr[0] + sAr[1] + sAr[2] + sAr[3];
        const float SV = sVr[0] + sVr[1] + sVr[2] + sVr[3];
        const float inv = 1.0f / fmaxf(SV, 1e-12f * SA);
        s_inv = inv;
        g_M[b]   = M;           // both blocks of b write identical values
        g_inv[b] = inv;
        g_A[b]   = SV * inv;
    }
    __syncthreads();
    const float inv = s_inv;

    // --- merge: thread owns h = hb + tid (coalesced) ---
    const float* P = g_part + (size_t)base * H_ + hb + tid;
    float acc = 0.f;
#pragma unroll 8
    for (int j = 0; j < CHUNKS_PER_B; j++)
        acc += s_scale[j] * P[(size_t)j * H_];
    g_ctxh[b * H_ + hb + tid] = acc * inv;
}

// ---------------------------------------------------------------------------
// Kernel 4: attention output.  Thread per (b,t): 512 blocks x 256.
// ---------------------------------------------------------------------------
__global__ void __launch_bounds__(256) k_attn(const int* __restrict__ lens,
                                              float* __restrict__ attn) {
    const int idx = blockIdx.x * 256 + threadIdx.x;
    const int b = idx >> 11;
    const int t = idx & (T_ - 1);
    const bool vd = (b == 0) || (t < lens[b]);
    attn[idx] = vd ? __expf(g_energy[idx] - g_M[b]) * g_inv[b] : 0.f;
}

// ---------------------------------------------------------------------------
// Kernel 5: output GEMM.  Warp per (b,v): 1024 blocks x 256.
// ---------------------------------------------------------------------------
__global__ void __launch_bounds__(256) k_out(const float* __restrict__ Wv,
                                             const float* __restrict__ bv,
                                             float* __restrict__ ctx) {
    const int w    = blockIdx.x * 8 + (threadIdx.x >> 5);
    const int lane = threadIdx.x & 31;
    const int b = w >> 7;
    const int v = w & (V_ - 1);

    const float4* c4 = (const float4*)(g_ctxh + b * H_);
    const float4* w4 = (const float4*)(Wv + v * H_);
    float acc = 0.f;
#pragma unroll
    for (int j = 0; j < 4; j++) {
        float4 wv = w4[lane + 32 * j];
        float4 cv = c4[lane + 32 * j];
        acc += wv.x * cv.x + wv.y * cv.y + wv.z * cv.z + wv.w * cv.w;
    }
    acc = warp_sum(acc);
    if (lane == 0) ctx[b * V_ + v] = acc + bv[v] * g_A[b];
}

// ---------------------------------------------------------------------------
extern "C" void kernel_launch(void* const* d_in, const int* in_sizes, int n_in,
                              void* d_out, int out_size) {
    const float* ds   = (const float*)d_in[0];  // decoder_state (B,S)
    const float* L    = (const float*)d_in[1];  // listener_output (B,T,H)
    const int*   lens = (const int*)  d_in[2];  // outputs_length (B,)
    const float* Ws   = (const float*)d_in[3];
    const float* bs   = (const float*)d_in[4];
    const float* Wh   = (const float*)d_in[5];
    const float* bh   = (const float*)d_in[6];
    const float* Wv   = (const float*)d_in[7];
    const float* bv   = (const float*)d_in[8];

    float* ctx  = (float*)d_out;            // (B,V)   = 8192 floats
    float* attn = ctx + B_ * V_;            // (B,1,T) = 131072 floats

    k_query<<<(B_ * K_) / 8, 256>>>(ds, Ws, bs);
    k_qh   <<<(B_ * H_) / 256, 256>>>(Wh, bh);
    k_flash<<<NWARPS_TOT / 8, 256>>>(L, lens);
    k_merge<<<(B_ * H_) / 256, 256>>>();
    k_attn <<<(B_ * T_) / 256, 256>>>(lens, attn);
    k_out  <<<(B_ * V_) / 8, 256>>>(Wv, bv, ctx);
}

// round 14
// speedup vs baseline: 1.1771x; 1.1771x over previous
#include <cuda_runtime.h>
#include <cstdint>

// Problem constants
#define B_  64
#define T_  2048
#define H_  512
#define S_  512
#define K_  128
#define V_  128

#define ROWS_PER_WARP 16
#define CHUNKS_PER_B  (T_ / ROWS_PER_WARP)          // 128
#define NWARPS_TOT    (B_ * CHUNKS_PER_B)           // 8192
#define GROUPS 4
#define JPG (CHUNKS_PER_B / GROUPS)                 // 32

// Scratch (device globals — no allocation allowed)
__device__ float g_q [B_ * K_];                 // query = ds@Ws^T + bs
__device__ float g_qh[B_ * H_];                 // Wh^T @ query per batch
__device__ float g_qc[B_];                      // query . bh
__device__ float g_energy[B_ * T_];             // raw energies
__device__ float g_pM [NWARPS_TOT];             // per-warp partial max
__device__ float g_pSA[NWARPS_TOT];             // per-warp partial sum(all exp)
__device__ float g_pSV[NWARPS_TOT];             // per-warp partial sum(valid exp)
__device__ float g_part[NWARPS_TOT * H_];       // per-warp partial weighted L sums
__device__ float g_pc[B_ * GROUPS * H_];        // group-partial merged sums
__device__ float g_ctxh[B_ * H_];               // merged, inv-scaled context in H
__device__ float g_M[B_], g_inv[B_], g_A[B_];   // per-batch softmax stats

__device__ __forceinline__ float warp_sum(float v) {
#pragma unroll
    for (int o = 16; o; o >>= 1) v += __shfl_xor_sync(0xffffffffu, v, o);
    return v;
}
__device__ __forceinline__ void warp_sum2(float& a, float& b) {
#pragma unroll
    for (int o = 16; o; o >>= 1) {
        a += __shfl_xor_sync(0xffffffffu, a, o);
        b += __shfl_xor_sync(0xffffffffu, b, o);
    }
}
__device__ __forceinline__ float warp_max(float v) {
#pragma unroll
    for (int o = 16; o; o >>= 1) v = fmaxf(v, __shfl_xor_sync(0xffffffffu, v, o));
    return v;
}

// ---------------------------------------------------------------------------
// Kernel 1a: query[b,k] = ds[b] . Ws[k] + bs[k].  Warp per (b,k).
// ---------------------------------------------------------------------------
__global__ void __launch_bounds__(256) k_query(const float* __restrict__ ds,
                                               const float* __restrict__ Ws,
                                               const float* __restrict__ bs) {
    const int w    = blockIdx.x * 8 + (threadIdx.x >> 5);
    const int lane = threadIdx.x & 31;
    const int b = w >> 7;
    const int k = w & (K_ - 1);

    const float4* d4 = (const float4*)(ds + b * S_);
    const float4* w4 = (const float4*)(Ws + k * S_);
    float acc = 0.f;
#pragma unroll
    for (int j = 0; j < 4; j++) {
        float4 dv = d4[lane + 32 * j];
        float4 wv = w4[lane + 32 * j];
        acc += dv.x * wv.x + dv.y * wv.y + dv.z * wv.z + dv.w * wv.w;
    }
    acc = warp_sum(acc);
    if (lane == 0) g_q[b * K_ + k] = acc + bs[k];
}

// ---------------------------------------------------------------------------
// Kernel 1b: qh[b,h] = sum_k q[b,k]*Wh[k,h] (thread per (b,h)); qc folded in.
// ---------------------------------------------------------------------------
__global__ void __launch_bounds__(256) k_qh(const float* __restrict__ Wh,
                                            const float* __restrict__ bh) {
    const int tid = threadIdx.x;
    const int idx = blockIdx.x * 256 + tid;
    const int b = idx >> 9;
    const int h = idx & (H_ - 1);

    const float* q = g_q + b * K_;
    const float* whc = Wh + h;
    float acc = 0.f;
#pragma unroll 8
    for (int k = 0; k < K_; k++)
        acc += q[k] * whc[k * H_];
    g_qh[b * H_ + h] = acc;

    if ((blockIdx.x & 1) == 0 && tid < 32) {
        float4 qv  = ((const float4*)q)[tid];
        float4 bhv = ((const float4*)bh)[tid];
        float p = qv.x * bhv.x + qv.y * bhv.y + qv.z * bhv.z + qv.w * bhv.w;
        p = warp_sum(p);
        if (tid == 0) g_qc[b] = p;
    }
}

// ---------------------------------------------------------------------------
// Kernel 2: warp-level flash pass (R10 version — measured best).  16 t-rows
// per warp, pairs, warp-uniform branchy rescale.  1024 blocks x 256 threads.
// ---------------------------------------------------------------------------
__global__ void __launch_bounds__(256) k_flash(const float* __restrict__ L,
                                               const int* __restrict__ lens) {
    const int w    = blockIdx.x * 8 + (threadIdx.x >> 5);
    const int lane = threadIdx.x & 31;
    const int b    = w >> 7;                       // / CHUNKS_PER_B
    const int t0   = (w & (CHUNKS_PER_B - 1)) * ROWS_PER_WARP;
    const int len  = lens[b];
    const int nv   = (b == 0) ? ROWS_PER_WARP
                              : min(max(len - t0, 0), ROWS_PER_WARP);

    const float4* qh4 = (const float4*)(g_qh + b * H_);
    const float4 q0 = qh4[lane +  0];
    const float4 q1 = qh4[lane + 32];
    const float4 q2 = qh4[lane + 64];
    const float4 q3 = qh4[lane + 96];
    const float  qc = g_qc[b];

    float M = __int_as_float(0xff800000), SA = 0.f, SV = 0.f;
    float4 a0 = make_float4(0.f, 0.f, 0.f, 0.f);
    float4 a1 = a0, a2 = a0, a3 = a0;

    const float4* Lr = (const float4*)(L + ((size_t)(b * T_ + t0)) * H_) + lane;

#pragma unroll 2
    for (int t = 0; t < ROWS_PER_WARP; t += 2) {
        const float4* rowA = Lr + (size_t)t * 128;
        const float4* rowB = rowA + 128;
        float4 la0 = rowA[0],  la1 = rowA[32], la2 = rowA[64], la3 = rowA[96];
        float4 lb0 = rowB[0],  lb1 = rowB[32], lb2 = rowB[64], lb3 = rowB[96];

        float eA = la0.x * q0.x + la0.y * q0.y + la0.z * q0.z + la0.w * q0.w
                 + la1.x * q1.x + la1.y * q1.y + la1.z * q1.z + la1.w * q1.w
                 + la2.x * q2.x + la2.y * q2.y + la2.z * q2.z + la2.w * q2.w
                 + la3.x * q3.x + la3.y * q3.y + la3.z * q3.z + la3.w * q3.w;
        float eB = lb0.x * q0.x + lb0.y * q0.y + lb0.z * q0.z + lb0.w * q0.w
                 + lb1.x * q1.x + lb1.y * q1.y + lb1.z * q1.z + lb1.w * q1.w
                 + lb2.x * q2.x + lb2.y * q2.y + lb2.z * q2.z + lb2.w * q2.w
                 + lb3.x * q3.x + lb3.y * q3.y + lb3.z * q3.z + lb3.w * q3.w;
        warp_sum2(eA, eB);
        eA += qc; eB += qc;
        if (lane == 0) {
            g_energy[b * T_ + t0 + t]     = eA;
            g_energy[b * T_ + t0 + t + 1] = eB;
        }

        const float mN = fmaxf(M, fmaxf(eA, eB));
        if (mN > M) {                            // warp-uniform
            const float f = __expf(M - mN);      // first pair: exp(-inf)=0
            SA *= f; SV *= f;
            a0.x *= f; a0.y *= f; a0.z *= f; a0.w *= f;
            a1.x *= f; a1.y *= f; a1.z *= f; a1.w *= f;
            a2.x *= f; a2.y *= f; a2.z *= f; a2.w *= f;
            a3.x *= f; a3.y *= f; a3.z *= f; a3.w *= f;
            M = mN;
        }
        const float xA = __expf(eA - M);
        const float xB = __expf(eB - M);
        const float xmA = (t     < nv) ? xA : 0.f;
        const float xmB = (t + 1 < nv) ? xB : 0.f;
        SA += xA + xB;
        SV += xmA + xmB;
        a0.x += xmA * la0.x + xmB * lb0.x;  a0.y += xmA * la0.y + xmB * lb0.y;
        a0.z += xmA * la0.z + xmB * lb0.z;  a0.w += xmA * la0.w + xmB * lb0.w;
        a1.x += xmA * la1.x + xmB * lb1.x;  a1.y += xmA * la1.y + xmB * lb1.y;
        a1.z += xmA * la1.z + xmB * lb1.z;  a1.w += xmA * la1.w + xmB * lb1.w;
        a2.x += xmA * la2.x + xmB * lb2.x;  a2.y += xmA * la2.y + xmB * lb2.y;
        a2.z += xmA * la2.z + xmB * lb2.z;  a2.w += xmA * la2.w + xmB * lb2.w;
        a3.x += xmA * la3.x + xmB * lb3.x;  a3.y += xmA * la3.y + xmB * lb3.y;
        a3.z += xmA * la3.z + xmB * lb3.z;  a3.w += xmA * la3.w + xmB * lb3.w;
    }

    if (lane == 0) { g_pM[w] = M; g_pSA[w] = SA; g_pSV[w] = SV; }
    float4* P = (float4*)(g_part + (size_t)w * H_) + lane;
    P[0]  = a0;
    P[32] = a1;
    P[64] = a2;
    P[96] = a3;
}

// ---------------------------------------------------------------------------
// Kernel 3a: group-partial merge.  Block = (b, j-group of 32 chunks, h-half).
// 512 blocks x 256 threads — 4x the parallelism of the old merge.
// Per-batch stats computed redundantly in-block (1.5 KB); the (g=0,h=0)
// block of each batch writes g_M/g_inv/g_A.
// ---------------------------------------------------------------------------
__global__ void __launch_bounds__(256) k_merge1(void) {
    const int blk = blockIdx.x;             // 0..511
    const int b   = blk >> 3;
    const int g   = (blk >> 1) & 3;
    const int hb  = (blk & 1) << 8;
    const int tid = threadIdx.x;
    const int base = b * CHUNKS_PER_B;

    __shared__ float s_scale[CHUNKS_PER_B];
    __shared__ float s_red[4];
    __shared__ float s_M;

    const float NEG_INF = __int_as_float(0xff800000);
    const float m = (tid < CHUNKS_PER_B) ? g_pM[base + tid] : NEG_INF;
    float wm = warp_max(m);
    if (tid < CHUNKS_PER_B && (tid & 31) == 0) s_red[tid >> 5] = wm;
    __syncthreads();
    if (tid == 0)
        s_M = fmaxf(fmaxf(s_red[0], s_red[1]), fmaxf(s_red[2], s_red[3]));
    __syncthreads();
    const float M = s_M;
    if (tid < CHUNKS_PER_B) s_scale[tid] = __expf(m - M);
    __syncthreads();

    if (g == 0 && hb == 0) {
        float sa = 0.f, sv = 0.f;
        if (tid < CHUNKS_PER_B) {
            sa = s_scale[tid] * g_pSA[base + tid];
            sv = s_scale[tid] * g_pSV[base + tid];
        }
        warp_sum2(sa, sv);
        __shared__ float sAr[4], sVr[4];
        if (tid < CHUNKS_PER_B && (tid & 31) == 0) {
            sAr[tid >> 5] = sa; sVr[tid >> 5] = sv;
        }
        __syncthreads();
        if (tid == 0) {
            const float SA = sAr[0] + sAr[1] + sAr[2] + sAr[3];
            const float SV = sVr[0] + sVr[1] + sVr[2] + sVr[3];
            const float inv = 1.0f / fmaxf(SV, 1e-12f * SA);
            g_M[b]   = M;
            g_inv[b] = inv;
            g_A[b]   = SV * inv;
        }
    }

    // partial merge over this block's 32 chunks (coalesced in h)
    const float* P = g_part + ((size_t)(base + g * JPG)) * H_ + hb + tid;
    const float* SC = s_scale + g * JPG;
    float acc = 0.f;
#pragma unroll 8
    for (int j = 0; j < JPG; j++)
        acc += SC[j] * P[(size_t)j * H_];
    g_pc[((b * GROUPS + g) * H_) + hb + tid] = acc;
}

// ---------------------------------------------------------------------------
// Kernel 3b: final 4-way sum + inv scale.  128 blocks x 256 threads.
// ---------------------------------------------------------------------------
__global__ void __launch_bounds__(256) k_merge2(void) {
    const int idx = blockIdx.x * 256 + threadIdx.x;   // 0..32767  (= b*H + h)
    const int b = idx >> 9;
    const int h = idx & (H_ - 1);
    const float* pc = g_pc + (size_t)b * GROUPS * H_ + h;
    g_ctxh[idx] = (pc[0] + pc[H_] + pc[2 * H_] + pc[3 * H_]) * g_inv[b];
}

// ---------------------------------------------------------------------------
// Kernel 4: attention output.  Thread per (b,t): 512 blocks x 256.
// ---------------------------------------------------------------------------
__global__ void __launch_bounds__(256) k_attn(const int* __restrict__ lens,
                                              float* __restrict__ attn) {
    const int idx = blockIdx.x * 256 + threadIdx.x;
    const int b = idx >> 11;
    const int t = idx & (T_ - 1);
    const bool vd = (b == 0) || (t < lens[b]);
    attn[idx] = vd ? __expf(g_energy[idx] - g_M[b]) * g_inv[b] : 0.f;
}

// ---------------------------------------------------------------------------
// Kernel 5: output GEMM.  Warp per (b,v): 1024 blocks x 256.
// ---------------------------------------------------------------------------
__global__ void __launch_bounds__(256) k_out(const float* __restrict__ Wv,
                                             const float* __restrict__ bv,
                                             float* __restrict__ ctx) {
    const int w    = blockIdx.x * 8 + (threadIdx.x >> 5);
    const int lane = threadIdx.x & 31;
    const int b = w >> 7;
    const int v = w & (V_ - 1);

    const float4* c4 = (const float4*)(g_ctxh + b * H_);
    const float4* w4 = (const float4*)(Wv + v * H_);
    float acc = 0.f;
#pragma unroll
    for (int j = 0; j < 4; j++) {
        float4 wv = w4[lane + 32 * j];
        float4 cv = c4[lane + 32 * j];
        acc += wv.x * cv.x + wv.y * cv.y + wv.z * cv.z + wv.w * cv.w;
    }
    acc = warp_sum(acc);
    if (lane == 0) ctx[b * V_ + v] = acc + bv[v] * g_A[b];
}

// ---------------------------------------------------------------------------
extern "C" void kernel_launch(void* const* d_in, const int* in_sizes, int n_in,
                              void* d_out, int out_size) {
    const float* ds   = (const float*)d_in[0];  // decoder_state (B,S)
    const float* L    = (const float*)d_in[1];  // listener_output (B,T,H)
    const int*   lens = (const int*)  d_in[2];  // outputs_length (B,)
    const float* Ws   = (const float*)d_in[3];
    const float* bs   = (const float*)d_in[4];
    const float* Wh   = (const float*)d_in[5];
    const float* bh   = (const float*)d_in[6];
    const float* Wv   = (const float*)d_in[7];
    const float* bv   = (const float*)d_in[8];

    float* ctx  = (float*)d_out;            // (B,V)   = 8192 floats
    float* attn = ctx + B_ * V_;            // (B,1,T) = 131072 floats

    k_query <<<(B_ * K_) / 8, 256>>>(ds, Ws, bs);
    k_qh    <<<(B_ * H_) / 256, 256>>>(Wh, bh);
    k_flash <<<NWARPS_TOT / 8, 256>>>(L, lens);
    k_merge1<<<B_ * GROUPS * 2, 256>>>();
    k_merge2<<<(B_ * H_) / 256, 256>>>();
    k_attn  <<<(B_ * T_) / 256, 256>>>(lens, attn);
    k_out   <<<(B_ * V_) / 8, 256>>>(Wv, bv, ctx);
}

// round 15
// speedup vs baseline: 1.3537x; 1.1501x over previous
#include <cuda_runtime.h>
#include <cstdint>

// Problem constants
#define B_  64
#define T_  2048
#define H_  512
#define S_  512
#define K_  128
#define V_  128

#define ROWS_PER_WARP 16
#define CHUNKS_PER_B  (T_ / ROWS_PER_WARP)          // 128
#define NWARPS_TOT    (B_ * CHUNKS_PER_B)           // 8192
#define GROUPS 4
#define JPG (CHUNKS_PER_B / GROUPS)                 // 32

// Scratch (device globals — no allocation allowed)
__device__ float g_q [B_ * K_];                 // query = ds@Ws^T + bs
__device__ float g_qh[B_ * H_];                 // Wh^T @ query per batch
__device__ float g_qc[B_];                      // query . bh
__device__ float g_energy[B_ * T_];             // raw energies
__device__ float g_pM [NWARPS_TOT];             // per-warp partial max
__device__ float g_pSA[NWARPS_TOT];             // per-warp partial sum(all exp)
__device__ float g_pSV[NWARPS_TOT];             // per-warp partial sum(valid exp)
__device__ float g_part[NWARPS_TOT * H_];       // per-warp partial weighted L sums
__device__ float g_pc[B_ * GROUPS * H_];        // group-partial merged sums
__device__ float g_ctxh[B_ * H_];               // merged, inv-scaled context in H
__device__ float g_M[B_], g_inv[B_], g_A[B_];   // per-batch softmax stats

__device__ __forceinline__ float warp_sum(float v) {
#pragma unroll
    for (int o = 16; o; o >>= 1) v += __shfl_xor_sync(0xffffffffu, v, o);
    return v;
}
__device__ __forceinline__ void warp_sum2(float& a, float& b) {
#pragma unroll
    for (int o = 16; o; o >>= 1) {
        a += __shfl_xor_sync(0xffffffffu, a, o);
        b += __shfl_xor_sync(0xffffffffu, b, o);
    }
}
__device__ __forceinline__ float warp_max(float v) {
#pragma unroll
    for (int o = 16; o; o >>= 1) v = fmaxf(v, __shfl_xor_sync(0xffffffffu, v, o));
    return v;
}

// ---------------------------------------------------------------------------
// Kernel 1a: query[b,k] = ds[b] . Ws[k] + bs[k].  Warp per (b,k).
// ---------------------------------------------------------------------------
__global__ void __launch_bounds__(256) k_query(const float* __restrict__ ds,
                                               const float* __restrict__ Ws,
                                               const float* __restrict__ bs) {
    const int w    = blockIdx.x * 8 + (threadIdx.x >> 5);
    const int lane = threadIdx.x & 31;
    const int b = w >> 7;
    const int k = w & (K_ - 1);

    const float4* d4 = (const float4*)(ds + b * S_);
    const float4* w4 = (const float4*)(Ws + k * S_);
    float acc = 0.f;
#pragma unroll
    for (int j = 0; j < 4; j++) {
        float4 dv = d4[lane + 32 * j];
        float4 wv = w4[lane + 32 * j];
        acc += dv.x * wv.x + dv.y * wv.y + dv.z * wv.z + dv.w * wv.w;
    }
    acc = warp_sum(acc);
    if (lane == 0) g_q[b * K_ + k] = acc + bs[k];
}

// ---------------------------------------------------------------------------
// Kernel 1b: qh[b,h] = sum_k q[b,k]*Wh[k,h] (thread per (b,h)); qc folded in.
// ---------------------------------------------------------------------------
__global__ void __launch_bounds__(256) k_qh(const float* __restrict__ Wh,
                                            const float* __restrict__ bh) {
    const int tid = threadIdx.x;
    const int idx = blockIdx.x * 256 + tid;
    const int b = idx >> 9;
    const int h = idx & (H_ - 1);

    const float* q = g_q + b * K_;
    const float* whc = Wh + h;
    float acc = 0.f;
#pragma unroll 8
    for (int k = 0; k < K_; k++)
        acc += q[k] * whc[k * H_];
    g_qh[b * H_ + h] = acc;

    if ((blockIdx.x & 1) == 0 && tid < 32) {
        float4 qv  = ((const float4*)q)[tid];
        float4 bhv = ((const float4*)bh)[tid];
        float p = qv.x * bhv.x + qv.y * bhv.y + qv.z * bhv.z + qv.w * bhv.w;
        p = warp_sum(p);
        if (tid == 0) g_qc[b] = p;
    }
}

// ---------------------------------------------------------------------------
// Kernel 2: warp-level flash pass.  Same math as the measured-best R10/R14
// version; changes: 128-thread blocks (5 blocks/SM -> 20 warps/SM instead of
// 16; finer wave granularity) and __ldcs evict-first loads on L (streamed
// once, never reused — keeps g_part/energy L2-resident for the merge).
// grid = 2048 blocks x 128 threads.
// ---------------------------------------------------------------------------
__global__ void __launch_bounds__(128) k_flash(const float* __restrict__ L,
                                               const int* __restrict__ lens) {
    const int w    = blockIdx.x * 4 + (threadIdx.x >> 5);
    const int lane = threadIdx.x & 31;
    const int b    = w >> 7;                       // / CHUNKS_PER_B
    const int t0   = (w & (CHUNKS_PER_B - 1)) * ROWS_PER_WARP;
    const int len  = lens[b];
    const int nv   = (b == 0) ? ROWS_PER_WARP
                              : min(max(len - t0, 0), ROWS_PER_WARP);

    const float4* qh4 = (const float4*)(g_qh + b * H_);
    const float4 q0 = qh4[lane +  0];
    const float4 q1 = qh4[lane + 32];
    const float4 q2 = qh4[lane + 64];
    const float4 q3 = qh4[lane + 96];
    const float  qc = g_qc[b];

    float M = __int_as_float(0xff800000), SA = 0.f, SV = 0.f;
    float4 a0 = make_float4(0.f, 0.f, 0.f, 0.f);
    float4 a1 = a0, a2 = a0, a3 = a0;

    const float4* Lr = (const float4*)(L + ((size_t)(b * T_ + t0)) * H_) + lane;

#pragma unroll 2
    for (int t = 0; t < ROWS_PER_WARP; t += 2) {
        const float4* rowA = Lr + (size_t)t * 128;
        const float4* rowB = rowA + 128;
        float4 la0 = __ldcs(rowA +   0), la1 = __ldcs(rowA +  32);
        float4 la2 = __ldcs(rowA +  64), la3 = __ldcs(rowA +  96);
        float4 lb0 = __ldcs(rowB +   0), lb1 = __ldcs(rowB +  32);
        float4 lb2 = __ldcs(rowB +  64), lb3 = __ldcs(rowB +  96);

        float eA = la0.x * q0.x + la0.y * q0.y + la0.z * q0.z + la0.w * q0.w
                 + la1.x * q1.x + la1.y * q1.y + la1.z * q1.z + la1.w * q1.w
                 + la2.x * q2.x + la2.y * q2.y + la2.z * q2.z + la2.w * q2.w
                 + la3.x * q3.x + la3.y * q3.y + la3.z * q3.z + la3.w * q3.w;
        float eB = lb0.x * q0.x + lb0.y * q0.y + lb0.z * q0.z + lb0.w * q0.w
                 + lb1.x * q1.x + lb1.y * q1.y + lb1.z * q1.z + lb1.w * q1.w
                 + lb2.x * q2.x + lb2.y * q2.y + lb2.z * q2.z + lb2.w * q2.w
                 + lb3.x * q3.x + lb3.y * q3.y + lb3.z * q3.z + lb3.w * q3.w;
        warp_sum2(eA, eB);
        eA += qc; eB += qc;
        if (lane == 0) {
            g_energy[b * T_ + t0 + t]     = eA;
            g_energy[b * T_ + t0 + t + 1] = eB;
        }

        const float mN = fmaxf(M, fmaxf(eA, eB));
        if (mN > M) {                            // warp-uniform
            const float f = __expf(M - mN);      // first pair: exp(-inf)=0
            SA *= f; SV *= f;
            a0.x *= f; a0.y *= f; a0.z *= f; a0.w *= f;
            a1.x *= f; a1.y *= f; a1.z *= f; a1.w *= f;
            a2.x *= f; a2.y *= f; a2.z *= f; a2.w *= f;
            a3.x *= f; a3.y *= f; a3.z *= f; a3.w *= f;
            M = mN;
        }
        const float xA = __expf(eA - M);
        const float xB = __expf(eB - M);
        const float xmA = (t     < nv) ? xA : 0.f;
        const float xmB = (t + 1 < nv) ? xB : 0.f;
        SA += xA + xB;
        SV += xmA + xmB;
        a0.x += xmA * la0.x + xmB * lb0.x;  a0.y += xmA * la0.y + xmB * lb0.y;
        a0.z += xmA * la0.z + xmB * lb0.z;  a0.w += xmA * la0.w + xmB * lb0.w;
        a1.x += xmA * la1.x + xmB * lb1.x;  a1.y += xmA * la1.y + xmB * lb1.y;
        a1.z += xmA * la1.z + xmB * lb1.z;  a1.w += xmA * la1.w + xmB * lb1.w;
        a2.x += xmA * la2.x + xmB * lb2.x;  a2.y += xmA * la2.y + xmB * lb2.y;
        a2.z += xmA * la2.z + xmB * lb2.z;  a2.w += xmA * la2.w + xmB * lb2.w;
        a3.x += xmA * la3.x + xmB * lb3.x;  a3.y += xmA * la3.y + xmB * lb3.y;
        a3.z += xmA * la3.z + xmB * lb3.z;  a3.w += xmA * la3.w + xmB * lb3.w;
    }

    if (lane == 0) { g_pM[w] = M; g_pSA[w] = SA; g_pSV[w] = SV; }
    float4* P = (float4*)(g_part + (size_t)w * H_) + lane;
    P[0]  = a0;
    P[32] = a1;
    P[64] = a2;
    P[96] = a3;
}

// ---------------------------------------------------------------------------
// Kernel 3a: group-partial merge.  Block = (b, j-group of 32 chunks, h-half).
// 512 blocks x 256 threads.  Per-batch stats computed redundantly in-block;
// the (g=0,h=0) block of each batch writes g_M/g_inv/g_A.
// ---------------------------------------------------------------------------
__global__ void __launch_bounds__(256) k_merge1(void) {
    const int blk = blockIdx.x;             // 0..511
    const int b   = blk >> 3;
    const int g   = (blk >> 1) & 3;
    const int hb  = (blk & 1) << 8;
    const int tid = threadIdx.x;
    const int base = b * CHUNKS_PER_B;

    __shared__ float s_scale[CHUNKS_PER_B];
    __shared__ float s_red[4];
    __shared__ float s_M;

    const float NEG_INF = __int_as_float(0xff800000);
    const float m = (tid < CHUNKS_PER_B) ? g_pM[base + tid] : NEG_INF;
    float wm = warp_max(m);
    if (tid < CHUNKS_PER_B && (tid & 31) == 0) s_red[tid >> 5] = wm;
    __syncthreads();
    if (tid == 0)
        s_M = fmaxf(fmaxf(s_red[0], s_red[1]), fmaxf(s_red[2], s_red[3]));
    __syncthreads();
    const float M = s_M;
    if (tid < CHUNKS_PER_B) s_scale[tid] = __expf(m - M);
    __syncthreads();

    if (g == 0 && hb == 0) {
        float sa = 0.f, sv = 0.f;
        if (tid < CHUNKS_PER_B) {
            sa = s_scale[tid] * g_pSA[base + tid];
            sv = s_scale[tid] * g_pSV[base + tid];
        }
        warp_sum2(sa, sv);
        __shared__ float sAr[4], sVr[4];
        if (tid < CHUNKS_PER_B && (tid & 31) == 0) {
            sAr[tid >> 5] = sa; sVr[tid >> 5] = sv;
        }
        __syncthreads();
        if (tid == 0) {
            const float SA = sAr[0] + sAr[1] + sAr[2] + sAr[3];
            const float SV = sVr[0] + sVr[1] + sVr[2] + sVr[3];
            const float inv = 1.0f / fmaxf(SV, 1e-12f * SA);
            g_M[b]   = M;
            g_inv[b] = inv;
            g_A[b]   = SV * inv;
        }
    }

    // partial merge over this block's 32 chunks (coalesced in h)
    const float* P = g_part + ((size_t)(base + g * JPG)) * H_ + hb + tid;
    const float* SC = s_scale + g * JPG;
    float acc = 0.f;
#pragma unroll 8
    for (int j = 0; j < JPG; j++)
        acc += SC[j] * P[(size_t)j * H_];
    g_pc[((b * GROUPS + g) * H_) + hb + tid] = acc;
}

// ---------------------------------------------------------------------------
// Kernel 3b: final 4-way sum + inv scale.  128 blocks x 256 threads.
// ---------------------------------------------------------------------------
__global__ void __launch_bounds__(256) k_merge2(void) {
    const int idx = blockIdx.x * 256 + threadIdx.x;   // 0..32767  (= b*H + h)
    const int b = idx >> 9;
    const int h = idx & (H_ - 1);
    const float* pc = g_pc + (size_t)b * GROUPS * H_ + h;
    g_ctxh[idx] = (pc[0] + pc[H_] + pc[2 * H_] + pc[3 * H_]) * g_inv[b];
}

// ---------------------------------------------------------------------------
// Kernel 4: attention output.  Thread per (b,t): 512 blocks x 256.
// ---------------------------------------------------------------------------
__global__ void __launch_bounds__(256) k_attn(const int* __restrict__ lens,
                                              float* __restrict__ attn) {
    const int idx = blockIdx.x * 256 + threadIdx.x;
    const int b = idx >> 11;
    const int t = idx & (T_ - 1);
    const bool vd = (b == 0) || (t < lens[b]);
    attn[idx] = vd ? __expf(g_energy[idx] - g_M[b]) * g_inv[b] : 0.f;
}

// ---------------------------------------------------------------------------
// Kernel 5: output GEMM.  Warp per (b,v): 1024 blocks x 256.
// ---------------------------------------------------------------------------
__global__ void __launch_bounds__(256) k_out(const float* __restrict__ Wv,
                                             const float* __restrict__ bv,
                                             float* __restrict__ ctx) {
    const int w    = blockIdx.x * 8 + (threadIdx.x >> 5);
    const int lane = threadIdx.x & 31;
    const int b = w >> 7;
    const int v = w & (V_ - 1);

    const float4* c4 = (const float4*)(g_ctxh + b * H_);
    const float4* w4 = (const float4*)(Wv + v * H_);
    float acc = 0.f;
#pragma unroll
    for (int j = 0; j < 4; j++) {
        float4 wv = w4[lane + 32 * j];
        float4 cv = c4[lane + 32 * j];
        acc += wv.x * cv.x + wv.y * cv.y + wv.z * cv.z + wv.w * cv.w;
    }
    acc = warp_sum(acc);
    if (lane == 0) ctx[b * V_ + v] = acc + bv[v] * g_A[b];
}

// ---------------------------------------------------------------------------
extern "C" void kernel_launch(void* const* d_in, const int* in_sizes, int n_in,
                              void* d_out, int out_size) {
    const float* ds   = (const float*)d_in[0];  // decoder_state (B,S)
    const float* L    = (const float*)d_in[1];  // listener_output (B,T,H)
    const int*   lens = (const int*)  d_in[2];  // outputs_length (B,)
    const float* Ws   = (const float*)d_in[3];
    const float* bs   = (const float*)d_in[4];
    const float* Wh   = (const float*)d_in[5];
    const float* bh   = (const float*)d_in[6];
    const float* Wv   = (const float*)d_in[7];
    const float* bv   = (const float*)d_in[8];

    float* ctx  = (float*)d_out;            // (B,V)   = 8192 floats
    float* attn = ctx + B_ * V_;            // (B,1,T) = 131072 floats

    k_query <<<(B_ * K_) / 8, 256>>>(ds, Ws, bs);
    k_qh    <<<(B_ * H_) / 256, 256>>>(Wh, bh);
    k_flash <<<NWARPS_TOT / 4, 128>>>(L, lens);
    k_merge1<<<B_ * GROUPS * 2, 256>>>();
    k_merge2<<<(B_ * H_) / 256, 256>>>();
    k_attn  <<<(B_ * T_) / 256, 256>>>(lens, attn);
    k_out   <<<(B_ * V_) / 8, 256>>>(Wv, bv, ctx);
}

// round 16
// speedup vs baseline: 1.4091x; 1.0409x over previous
#include <cuda_runtime.h>
#include <cstdint>

// Problem constants
#define B_  64
#define T_  2048
#define H_  512
#define S_  512
#define K_  128
#define V_  128

#define ROWS_PER_WARP 32
#define CHUNKS_PER_B  (T_ / ROWS_PER_WARP)          // 64
#define NWARPS_TOT    (B_ * CHUNKS_PER_B)           // 4096
#define GROUPS 4
#define JPG (CHUNKS_PER_B / GROUPS)                 // 16

// Scratch (device globals — no allocation allowed)
__device__ float g_q [B_ * K_];                 // query = ds@Ws^T + bs
__device__ float g_qh[B_ * H_];                 // Wh^T @ query per batch
__device__ float g_qc[B_];                      // query . bh
__device__ float g_energy[B_ * T_];             // raw energies
__device__ float g_pM [NWARPS_TOT];             // per-warp partial max
__device__ float g_pSA[NWARPS_TOT];             // per-warp partial sum(all exp)
__device__ float g_pSV[NWARPS_TOT];             // per-warp partial sum(valid exp)
__device__ float g_part[NWARPS_TOT * H_];       // per-warp partial weighted L sums (8 MB)
__device__ float g_pc[B_ * GROUPS * H_];        // group-partial merged sums
__device__ float g_ctxh[B_ * H_];               // merged, inv-scaled context in H
__device__ float g_M[B_], g_inv[B_], g_A[B_];   // per-batch softmax stats

__device__ __forceinline__ float warp_sum(float v) {
#pragma unroll
    for (int o = 16; o; o >>= 1) v += __shfl_xor_sync(0xffffffffu, v, o);
    return v;
}
__device__ __forceinline__ void warp_sum2(float& a, float& b) {
#pragma unroll
    for (int o = 16; o; o >>= 1) {
        a += __shfl_xor_sync(0xffffffffu, a, o);
        b += __shfl_xor_sync(0xffffffffu, b, o);
    }
}
__device__ __forceinline__ float warp_max(float v) {
#pragma unroll
    for (int o = 16; o; o >>= 1) v = fmaxf(v, __shfl_xor_sync(0xffffffffu, v, o));
    return v;
}

// ---------------------------------------------------------------------------
// Kernel 1a: query[b,k] = ds[b] . Ws[k] + bs[k].  Warp per (b,k).
// ---------------------------------------------------------------------------
__global__ void __launch_bounds__(256) k_query(const float* __restrict__ ds,
                                               const float* __restrict__ Ws,
                                               const float* __restrict__ bs) {
    const int w    = blockIdx.x * 8 + (threadIdx.x >> 5);
    const int lane = threadIdx.x & 31;
    const int b = w >> 7;
    const int k = w & (K_ - 1);

    const float4* d4 = (const float4*)(ds + b * S_);
    const float4* w4 = (const float4*)(Ws + k * S_);
    float acc = 0.f;
#pragma unroll
    for (int j = 0; j < 4; j++) {
        float4 dv = d4[lane + 32 * j];
        float4 wv = w4[lane + 32 * j];
        acc += dv.x * wv.x + dv.y * wv.y + dv.z * wv.z + dv.w * wv.w;
    }
    acc = warp_sum(acc);
    if (lane == 0) g_q[b * K_ + k] = acc + bs[k];
}

// ---------------------------------------------------------------------------
// Kernel 1b: qh[b,h] = sum_k q[b,k]*Wh[k,h] (thread per (b,h)); qc folded in.
// ---------------------------------------------------------------------------
__global__ void __launch_bounds__(256) k_qh(const float* __restrict__ Wh,
                                            const float* __restrict__ bh) {
    const int tid = threadIdx.x;
    const int idx = blockIdx.x * 256 + tid;
    const int b = idx >> 9;
    const int h = idx & (H_ - 1);

    const float* q = g_q + b * K_;
    const float* whc = Wh + h;
    float acc = 0.f;
#pragma unroll 8
    for (int k = 0; k < K_; k++)
        acc += q[k] * whc[k * H_];
    g_qh[b * H_ + h] = acc;

    if ((blockIdx.x & 1) == 0 && tid < 32) {
        float4 qv  = ((const float4*)q)[tid];
        float4 bhv = ((const float4*)bh)[tid];
        float p = qv.x * bhv.x + qv.y * bhv.y + qv.z * bhv.z + qv.w * bhv.w;
        p = warp_sum(p);
        if (tid == 0) g_qc[b] = p;
    }
}

// ---------------------------------------------------------------------------
// Kernel 2: warp-level flash pass.  32 t-rows per warp (halves the partial
// surface: 8 MB instead of 16 MB written here + re-read in merge).  Same
// per-iteration math / registers as the measured-best version; 128-thread
// blocks (5 blocks/SM = 20 warps/SM), __ldcs evict-first on streamed L.
// grid = 1024 blocks x 128 threads = 4096 warps.
// ---------------------------------------------------------------------------
__global__ void __launch_bounds__(128) k_flash(const float* __restrict__ L,
                                               const int* __restrict__ lens) {
    const int w    = blockIdx.x * 4 + (threadIdx.x >> 5);
    const int lane = threadIdx.x & 31;
    const int b    = w >> 6;                       // / CHUNKS_PER_B
    const int t0   = (w & (CHUNKS_PER_B - 1)) * ROWS_PER_WARP;
    const int len  = lens[b];
    const int nv   = (b == 0) ? ROWS_PER_WARP
                              : min(max(len - t0, 0), ROWS_PER_WARP);

    const float4* qh4 = (const float4*)(g_qh + b * H_);
    const float4 q0 = qh4[lane +  0];
    const float4 q1 = qh4[lane + 32];
    const float4 q2 = qh4[lane + 64];
    const float4 q3 = qh4[lane + 96];
    const float  qc = g_qc[b];

    float M = __int_as_float(0xff800000), SA = 0.f, SV = 0.f;
    float4 a0 = make_float4(0.f, 0.f, 0.f, 0.f);
    float4 a1 = a0, a2 = a0, a3 = a0;

    const float4* Lr = (const float4*)(L + ((size_t)(b * T_ + t0)) * H_) + lane;

#pragma unroll 2
    for (int t = 0; t < ROWS_PER_WARP; t += 2) {
        const float4* rowA = Lr + (size_t)t * 128;
        const float4* rowB = rowA + 128;
        float4 la0 = __ldcs(rowA +   0), la1 = __ldcs(rowA +  32);
        float4 la2 = __ldcs(rowA +  64), la3 = __ldcs(rowA +  96);
        float4 lb0 = __ldcs(rowB +   0), lb1 = __ldcs(rowB +  32);
        float4 lb2 = __ldcs(rowB +  64), lb3 = __ldcs(rowB +  96);

        float eA = la0.x * q0.x + la0.y * q0.y + la0.z * q0.z + la0.w * q0.w
                 + la1.x * q1.x + la1.y * q1.y + la1.z * q1.z + la1.w * q1.w
                 + la2.x * q2.x + la2.y * q2.y + la2.z * q2.z + la2.w * q2.w
                 + la3.x * q3.x + la3.y * q3.y + la3.z * q3.z + la3.w * q3.w;
        float eB = lb0.x * q0.x + lb0.y * q0.y + lb0.z * q0.z + lb0.w * q0.w
                 + lb1.x * q1.x + lb1.y * q1.y + lb1.z * q1.z + lb1.w * q1.w
                 + lb2.x * q2.x + lb2.y * q2.y + lb2.z * q2.z + lb2.w * q2.w
                 + lb3.x * q3.x + lb3.y * q3.y + lb3.z * q3.z + lb3.w * q3.w;
        warp_sum2(eA, eB);
        eA += qc; eB += qc;
        if (lane == 0) {
            g_energy[b * T_ + t0 + t]     = eA;
            g_energy[b * T_ + t0 + t + 1] = eB;
        }

        const float mN = fmaxf(M, fmaxf(eA, eB));
        if (mN > M) {                            // warp-uniform
            const float f = __expf(M - mN);      // first pair: exp(-inf)=0
            SA *= f; SV *= f;
            a0.x *= f; a0.y *= f; a0.z *= f; a0.w *= f;
            a1.x *= f; a1.y *= f; a1.z *= f; a1.w *= f;
            a2.x *= f; a2.y *= f; a2.z *= f; a2.w *= f;
            a3.x *= f; a3.y *= f; a3.z *= f; a3.w *= f;
            M = mN;
        }
        const float xA = __expf(eA - M);
        const float xB = __expf(eB - M);
        const float xmA = (t     < nv) ? xA : 0.f;
        const float xmB = (t + 1 < nv) ? xB : 0.f;
        SA += xA + xB;
        SV += xmA + xmB;
        a0.x += xmA * la0.x + xmB * lb0.x;  a0.y += xmA * la0.y + xmB * lb0.y;
        a0.z += xmA * la0.z + xmB * lb0.z;  a0.w += xmA * la0.w + xmB * lb0.w;
        a1.x += xmA * la1.x + xmB * lb1.x;  a1.y += xmA * la1.y + xmB * lb1.y;
        a1.z += xmA * la1.z + xmB * lb1.z;  a1.w += xmA * la1.w + xmB * lb1.w;
        a2.x += xmA * la2.x + xmB * lb2.x;  a2.y += xmA * la2.y + xmB * lb2.y;
        a2.z += xmA * la2.z + xmB * lb2.z;  a2.w += xmA * la2.w + xmB * lb2.w;
        a3.x += xmA * la3.x + xmB * lb3.x;  a3.y += xmA * la3.y + xmB * lb3.y;
        a3.z += xmA * la3.z + xmB * lb3.z;  a3.w += xmA * la3.w + xmB * lb3.w;
    }

    if (lane == 0) { g_pM[w] = M; g_pSA[w] = SA; g_pSV[w] = SV; }
    float4* P = (float4*)(g_part + (size_t)w * H_) + lane;
    P[0]  = a0;
    P[32] = a1;
    P[64] = a2;
    P[96] = a3;
}

// ---------------------------------------------------------------------------
// Kernel 3a: group-partial merge.  Block = (b, j-group of 16 chunks, h-half).
// 512 blocks x 256 threads, now over 8 MB of partials (half of before).
// Per-batch stats computed redundantly in-block; the (g=0,h=0) block of each
// batch writes g_M/g_inv/g_A.
// ---------------------------------------------------------------------------
__global__ void __launch_bounds__(256) k_merge1(void) {
    const int blk = blockIdx.x;             // 0..511
    const int b   = blk >> 3;
    const int g   = (blk >> 1) & 3;
    const int hb  = (blk & 1) << 8;
    const int tid = threadIdx.x;
    const int base = b * CHUNKS_PER_B;

    __shared__ float s_scale[CHUNKS_PER_B];
    __shared__ float s_red[2];
    __shared__ float s_M;

    const float NEG_INF = __int_as_float(0xff800000);
    const float m = (tid < CHUNKS_PER_B) ? g_pM[base + tid] : NEG_INF;
    if (tid < CHUNKS_PER_B) {
        float wm = warp_max(m);
        if ((tid & 31) == 0) s_red[tid >> 5] = wm;
    }
    __syncthreads();
    if (tid == 0) s_M = fmaxf(s_red[0], s_red[1]);
    __syncthreads();
    const float M = s_M;
    if (tid < CHUNKS_PER_B) s_scale[tid] = __expf(m - M);
    __syncthreads();

    if (g == 0 && hb == 0) {
        float sa = 0.f, sv = 0.f;
        __shared__ float sAr[2], sVr[2];
        if (tid < CHUNKS_PER_B) {
            sa = s_scale[tid] * g_pSA[base + tid];
            sv = s_scale[tid] * g_pSV[base + tid];
            warp_sum2(sa, sv);
            if ((tid & 31) == 0) { sAr[tid >> 5] = sa; sVr[tid >> 5] = sv; }
        }
        __syncthreads();
        if (tid == 0) {
            const float SA = sAr[0] + sAr[1];
            const float SV = sVr[0] + sVr[1];
            const float inv = 1.0f / fmaxf(SV, 1e-12f * SA);
            g_M[b]   = M;
            g_inv[b] = inv;
            g_A[b]   = SV * inv;
        }
    }

    // partial merge over this block's 16 chunks (coalesced in h)
    const float* P = g_part + ((size_t)(base + g * JPG)) * H_ + hb + tid;
    const float* SC = s_scale + g * JPG;
    float acc = 0.f;
#pragma unroll
    for (int j = 0; j < JPG; j++)
        acc += SC[j] * P[(size_t)j * H_];
    g_pc[((b * GROUPS + g) * H_) + hb + tid] = acc;
}

// ---------------------------------------------------------------------------
// Kernel 3b: final 4-way sum + inv scale.  128 blocks x 256 threads.
// ---------------------------------------------------------------------------
__global__ void __launch_bounds__(256) k_merge2(void) {
    const int idx = blockIdx.x * 256 + threadIdx.x;   // 0..32767  (= b*H + h)
    const int b = idx >> 9;
    const int h = idx & (H_ - 1);
    const float* pc = g_pc + (size_t)b * GROUPS * H_ + h;
    g_ctxh[idx] = (pc[0] + pc[H_] + pc[2 * H_] + pc[3 * H_]) * g_inv[b];
}

// ---------------------------------------------------------------------------
// Kernel 4: attention output.  Thread per (b,t): 512 blocks x 256.
// ---------------------------------------------------------------------------
__global__ void __launch_bounds__(256) k_attn(const int* __restrict__ lens,
                                              float* __restrict__ attn) {
    const int idx = blockIdx.x * 256 + threadIdx.x;
    const int b = idx >> 11;
    const int t = idx & (T_ - 1);
    const bool vd = (b == 0) || (t < lens[b]);
    attn[idx] = vd ? __expf(g_energy[idx] - g_M[b]) * g_inv[b] : 0.f;
}

// ---------------------------------------------------------------------------
// Kernel 5: output GEMM.  Warp per (b,v): 1024 blocks x 256.
// ---------------------------------------------------------------------------
__global__ void __launch_bounds__(256) k_out(const float* __restrict__ Wv,
                                             const float* __restrict__ bv,
                                             float* __restrict__ ctx) {
    const int w    = blockIdx.x * 8 + (threadIdx.x >> 5);
    const int lane = threadIdx.x & 31;
    const int b = w >> 7;
    const int v = w & (V_ - 1);

    const float4* c4 = (const float4*)(g_ctxh + b * H_);
    const float4* w4 = (const float4*)(Wv + v * H_);
    float acc = 0.f;
#pragma unroll
    for (int j = 0; j < 4; j++) {
        float4 wv = w4[lane + 32 * j];
        float4 cv = c4[lane + 32 * j];
        acc += wv.x * cv.x + wv.y * cv.y + wv.z * cv.z + wv.w * cv.w;
    }
    acc = warp_sum(acc);
    if (lane == 0) ctx[b * V_ + v] = acc + bv[v] * g_A[b];
}

// ---------------------------------------------------------------------------
extern "C" void kernel_launch(void* const* d_in, const int* in_sizes, int n_in,
                              void* d_out, int out_size) {
    const float* ds   = (const float*)d_in[0];  // decoder_state (B,S)
    const float* L    = (const float*)d_in[1];  // listener_output (B,T,H)
    const int*   lens = (const int*)  d_in[2];  // outputs_length (B,)
    const float* Ws   = (const float*)d_in[3];
    const float* bs   = (const float*)d_in[4];
    const float* Wh   = (const float*)d_in[5];
    const float* bh   = (const float*)d_in[6];
    const float* Wv   = (const float*)d_in[7];
    const float* bv   = (const float*)d_in[8];

    float* ctx  = (float*)d_out;            // (B,V)   = 8192 floats
    float* attn = ctx + B_ * V_;            // (B,1,T) = 131072 floats

    k_query <<<(B_ * K_) / 8, 256>>>(ds, Ws, bs);
    k_qh    <<<(B_ * H_) / 256, 256>>>(Wh, bh);
    k_flash <<<NWARPS_TOT / 4, 128>>>(L, lens);
    k_merge1<<<B_ * GROUPS * 2, 256>>>();
    k_merge2<<<(B_ * H_) / 256, 256>>>();
    k_attn  <<<(B_ * T_) / 256, 256>>>(lens, attn);
    k_out   <<<(B_ * V_) / 8, 256>>>(Wv, bv, ctx);
}